// round 13
// baseline (speedup 1.0000x reference)
#include <cuda_runtime.h>
#include <cstdint>

// MaxUnpooling2D: updates [16,64,64,256] f32, mask [16,64,64,256] i32
// (flattened per-batch output index), out [16,128,128,256] f32.
//
// Fused zero-fill + scatter (each pooled element owns its 2x2 window).
//
// R13: cross-replay L2 residency, take 2. sm_100 ptxas requires v8.b32 for
// L2::evict_last, so reuse R8's validated 8-channel/thread v8 structure and
// add evict_last to the two input loads. Inputs (134MB) nearly fit in L2
// (126MB) and are re-read every graph replay; evict_last pins them while
// normal-priority write-once output lines evict first.

#define C_  256
#define WO_ 128
#define HOWOC_ (128 * 128 * 256)   // per-batch output elements

__device__ __forceinline__ void ldg_v8_evict_last(const void* p, uint32_t r[8]) {
    asm volatile("ld.global.L2::evict_last.v8.b32 {%0,%1,%2,%3,%4,%5,%6,%7}, [%8];"
        : "=r"(r[0]), "=r"(r[1]), "=r"(r[2]), "=r"(r[3]),
          "=r"(r[4]), "=r"(r[5]), "=r"(r[6]), "=r"(r[7])
        : "l"(p));
}

__device__ __forceinline__ void stg_v8(void* p, const uint32_t r[8]) {
    asm volatile("st.global.v8.b32 [%0], {%1,%2,%3,%4,%5,%6,%7,%8};"
        :: "l"(p),
           "r"(r[0]), "r"(r[1]), "r"(r[2]), "r"(r[3]),
           "r"(r[4]), "r"(r[5]), "r"(r[6]), "r"(r[7])
        : "memory");
}

__global__ void __launch_bounds__(512) max_unpool_kernel(
    const uint32_t* __restrict__ upd,
    const int*      __restrict__ msk,
    float*          __restrict__ out,
    int n8)
{
    int t = blockIdx.x * blockDim.x + threadIdx.x;
    if (t >= n8) return;

    // One 32B load each (warp: 1024B dense bursts), pinned in L2.
    uint32_t mu[8], uu[8];
    ldg_v8_evict_last(msk + 8 * t, mu);
    ldg_v8_evict_last(upd + 8 * t, uu);

    // Decode: bit layout of t: c8 [0,5), w [5,11), h [11,17), b [17,21).
    int c8 = t & 31;
    int w  = (t >> 5)  & 63;
    int h  = (t >> 11) & 63;
    int b  = t >> 17;

    // Per-batch flattened address of window cell (0,0), channel 8*c8.
    int base = h * (2 * WO_ * C_) + w * (2 * C_) + (c8 << 3);

    float* ob = out + (size_t)b * HOWOC_ + base;

    // Window-cell offsets: (di*Wo + dj)*C for (di,dj) in {0,1}^2.
    const int offs[4] = {0, C_, WO_ * C_, WO_ * C_ + C_};

#pragma unroll
    for (int k = 0; k < 4; k++) {
        int a = base + offs[k];
        uint32_t v[8];
#pragma unroll
        for (int j = 0; j < 8; j++)
            v[j] = ((int)mu[j] == a + j) ? uu[j] : 0u;
        stg_v8(ob + offs[k], v);
    }
}

extern "C" void kernel_launch(void* const* d_in, const int* in_sizes, int n_in,
                              void* d_out, int out_size)
{
    const uint32_t* upd = (const uint32_t*)d_in[0];
    const int*      msk = (const int*)d_in[1];
    float*          out = (float*)d_out;

    int n  = in_sizes[0];       // 16*64*64*256 = 16,777,216
    int n8 = n >> 3;            // 2,097,152 work items (8 channels each)

    int threads = 512;
    int blocks  = (n8 + threads - 1) / threads;   // 4096
    max_unpool_kernel<<<blocks, threads>>>(upd, msk, out, n8);
}

// round 16
// speedup vs baseline: 1.0098x; 1.0098x over previous
#include <cuda_runtime.h>
#include <cstdint>

// MaxUnpooling2D: updates [16,64,64,256] f32, mask [16,64,64,256] i32
// (flattened per-batch output index), out [16,128,128,256] f32.
//
// Each pooled element scatters into its OWN 2x2 window at the SAME channel
// => output cells are covered exactly once. Fused zero-fill + scatter: each
// thread owns 4 channels of one pooled element and writes all 4 window
// cells as float4 (selected value or zero). Fully dense, fully coalesced.
//
// R5-R13 exhausted all levers (MLP, cache policy both directions, 256-bit
// width, r/w phasing, L2 pinning: all null; coalescing density: critical;
// block 512 > 256 by ~1%). Kernel sits at the HBM mixed-stream ceiling
// (~5.9TB/s raw, ~6.9TB/s effective on the 403MB logical floor).
// R14: final knob — block=1024 (4096 blocks, less scheduling overhead).
// R16: resubmit (rounds 14 and 15 were infra container failures; this
// variant is structurally identical to the proven 65.2us best).

#define C_  256
#define WO_ 128
#define HOWOC_ (128 * 128 * 256)   // per-batch output elements

__global__ void __launch_bounds__(1024) max_unpool_kernel(
    const float4* __restrict__ upd,
    const int4*   __restrict__ msk,
    float*        __restrict__ out,
    int n4)
{
    int t = blockIdx.x * blockDim.x + threadIdx.x;
    if (t >= n4) return;

    int4   m = __ldcs(msk + t);
    float4 u = __ldcs(upd + t);

    // Decode coords from linear float4 index. C/4 = 64, W = 64, H = 64.
    int c4 = t & 63;
    int w  = (t >> 6) & 63;
    int h  = (t >> 12) & 63;
    int b  = t >> 18;

    // Per-batch flattened base address of window cell (di=0, dj=0), channel 4*c4.
    int base = h * (2 * WO_ * C_) + w * (2 * C_) + (c4 << 2);

    float* ob = out + (size_t)b * HOWOC_ + base;

    // Window-cell offsets: (di*Wo + dj)*C for (di,dj) in {0,1}^2.
    const int offs[4] = {0, C_, WO_ * C_, WO_ * C_ + C_};

#pragma unroll
    for (int k = 0; k < 4; k++) {
        int a = base + offs[k];
        float4 v;
        v.x = (m.x == a + 0) ? u.x : 0.0f;
        v.y = (m.y == a + 1) ? u.y : 0.0f;
        v.z = (m.z == a + 2) ? u.z : 0.0f;
        v.w = (m.w == a + 3) ? u.w : 0.0f;
        __stcs(reinterpret_cast<float4*>(ob + offs[k]), v);
    }
}

extern "C" void kernel_launch(void* const* d_in, const int* in_sizes, int n_in,
                              void* d_out, int out_size)
{
    const float4* upd = (const float4*)d_in[0];
    const int4*   msk = (const int4*)d_in[1];
    float*        out = (float*)d_out;

    int n  = in_sizes[0];       // 16*64*64*256 = 16,777,216
    int n4 = n >> 2;            // 4,194,304 float4 work items

    int threads = 1024;
    int blocks  = (n4 + threads - 1) / threads;   // 4096
    max_unpool_kernel<<<blocks, threads>>>(upd, msk, out, n4);
}